// round 2
// baseline (speedup 1.0000x reference)
#include <cuda_runtime.h>
#include <math.h>

#define NNODES 50000
#define NEDGES 800000

// ---------------- scratch (device globals; no allocations allowed) ----------
__device__ int   g_degcur[2 * NNODES];          // degree, then CSR cursor
__device__ int   g_rowptr[2 * (NNODES + 1)];
__device__ int   g_csr_src[2 * NEDGES];
__device__ float g_csr_w[2 * NEDGES];
__device__ float g_norm[2 * NNODES];
__device__ float g_agg[NNODES * 128];
__device__ float g_hid[NNODES * 128];
__device__ float g_tmp[NNODES * 64];

// ---------------- graph preprocessing ---------------------------------------

__global__ void degree_kernel(const int* __restrict__ eA, const int* __restrict__ eB) {
    int i = blockIdx.x * blockDim.x + threadIdx.x;
    if (i >= 2 * NEDGES) return;
    int g = i / NEDGES, e = i - g * NEDGES;
    const int* ei = g ? eB : eA;
    int dst = ei[NEDGES + e];
    atomicAdd(&g_degcur[g * NNODES + dst], 1);
}

__global__ void norm_kernel() {
    int i = blockIdx.x * blockDim.x + threadIdx.x;
    if (i >= 2 * NNODES) return;
    g_norm[i] = rsqrtf((float)g_degcur[i] + 1.0f);
}

// one block per graph: exclusive scan of degrees -> rowptr, and init cursor
__global__ void scan_kernel() {
    __shared__ int sm[1024];
    int g = blockIdx.x;
    int t = threadIdx.x;
    const int CH = (NNODES + 1023) / 1024;   // 49
    int base = g * NNODES;
    int start = t * CH;
    int s = 0;
    for (int i = 0; i < CH; i++) {
        int idx = start + i;
        if (idx < NNODES) s += g_degcur[base + idx];
    }
    sm[t] = s;
    __syncthreads();
    // Hillis-Steele inclusive scan
    for (int d = 1; d < 1024; d <<= 1) {
        int v = sm[t];
        int add = (t >= d) ? sm[t - d] : 0;
        __syncthreads();
        sm[t] = v + add;
        __syncthreads();
    }
    int off = (t == 0) ? 0 : sm[t - 1];
    for (int i = 0; i < CH; i++) {
        int idx = start + i;
        if (idx < NNODES) {
            int d = g_degcur[base + idx];
            g_rowptr[g * (NNODES + 1) + idx] = off;
            g_degcur[base + idx] = off;          // cursor for fill
            off += d;
        }
    }
    if (t == 1023) g_rowptr[g * (NNODES + 1) + NNODES] = off;
}

__global__ void fill_kernel(const int* __restrict__ eA, const int* __restrict__ eB) {
    int i = blockIdx.x * blockDim.x + threadIdx.x;
    if (i >= 2 * NEDGES) return;
    int g = i / NEDGES, e = i - g * NEDGES;
    const int* ei = g ? eB : eA;
    int src = ei[e];
    int dst = ei[NEDGES + e];
    int pos = atomicAdd(&g_degcur[g * NNODES + dst], 1);
    g_csr_src[g * NEDGES + pos] = src;
    g_csr_w[g * NEDGES + pos]   = g_norm[g * NNODES + src] * g_norm[g * NNODES + dst];
}

// ---------------- GCN aggregation: warp per node -----------------------------
// out[i] = x[i]*norm[i]^2 + sum_{e: dst==i} x[src_e] * (norm[src]*norm[dst])
__global__ void agg_kernel(const float* __restrict__ x,
                           const int* __restrict__ rowptr,
                           const int* __restrict__ csrc,
                           const float* __restrict__ cw,
                           const float* __restrict__ nrm,
                           float* __restrict__ out) {
    int warp = (blockIdx.x * blockDim.x + threadIdx.x) >> 5;
    int lane = threadIdx.x & 31;
    if (warp >= NNODES) return;
    const float4* x4 = (const float4*)x;
    float nn = nrm[warp];
    float c = nn * nn;
    float4 a = x4[warp * 32 + lane];
    float4 acc;
    acc.x = a.x * c; acc.y = a.y * c; acc.z = a.z * c; acc.w = a.w * c;
    int b  = rowptr[warp];
    int en = rowptr[warp + 1];
    for (int e = b; e < en; e++) {
        int s   = __ldg(&csrc[e]);
        float w = __ldg(&cw[e]);
        float4 v = __ldg(&x4[s * 32 + lane]);
        acc.x += v.x * w; acc.y += v.y * w; acc.z += v.z * w; acc.w += v.w * w;
    }
    ((float4*)out)[warp * 32 + lane] = acc;
}

// ---------------- GEMM: Y[N x BN] = act( X[N x K] @ W[K x BN] + bias ) -------
// X may be a concat of X1 (K1 cols) and X2 (K2 cols).  BM=128, BK=16, 256 thr.
template <int BN>
__global__ void gemm_kernel(const float* __restrict__ X1, int K1,
                            const float* __restrict__ X2, int K2,
                            const float* __restrict__ W,
                            const float* __restrict__ bias,
                            float* __restrict__ Y, int n, int doRelu) {
    const int BM = 128, BK = 16, TM = 8, TN = BN / 16;
    __shared__ float As[BK][BM + 4];   // pad keeps float4 alignment, reduces STS conflicts
    __shared__ float Bs[BK][BN];
    int t  = threadIdx.x;
    int tx = t & 15;
    int ty = t >> 4;
    int row0 = blockIdx.x * BM;
    int K = K1 + K2;

    float acc[TM][TN];
#pragma unroll
    for (int i = 0; i < TM; i++)
#pragma unroll
        for (int j = 0; j < TN; j++) acc[i][j] = 0.0f;

    for (int k0 = 0; k0 < K; k0 += BK) {
        // load A tile
#pragma unroll
        for (int i = 0; i < (BM * BK) / 256; i++) {
            int e = i * 256 + t;
            int k = e & (BK - 1);
            int m = e >> 4;
            int row = row0 + m;
            int kg  = k0 + k;
            float v = 0.0f;
            if (row < n)
                v = (kg < K1) ? X1[row * K1 + kg] : X2[row * K2 + (kg - K1)];
            As[k][m] = v;
        }
        // load B tile
#pragma unroll
        for (int i = 0; i < (BK * BN) / 256; i++) {
            int e = i * 256 + t;
            int nn = e % BN;
            int k  = e / BN;
            Bs[k][nn] = W[(k0 + k) * BN + nn];
        }
        __syncthreads();
#pragma unroll
        for (int k = 0; k < BK; k++) {
            float rm[TM], rn[TN];
#pragma unroll
            for (int i = 0; i < TM; i++) rm[i] = As[k][ty * TM + i];
#pragma unroll
            for (int j = 0; j < TN; j++) rn[j] = Bs[k][tx * TN + j];
#pragma unroll
            for (int i = 0; i < TM; i++)
#pragma unroll
                for (int j = 0; j < TN; j++) acc[i][j] += rm[i] * rn[j];
        }
        __syncthreads();
    }

#pragma unroll
    for (int i = 0; i < TM; i++) {
        int row = row0 + ty * TM + i;
        if (row >= n) continue;
#pragma unroll
        for (int j = 0; j < TN; j += 4) {
            int col = tx * TN + j;
            float4 v;
            v.x = acc[i][j + 0] + bias[col + 0];
            v.y = acc[i][j + 1] + bias[col + 1];
            v.z = acc[i][j + 2] + bias[col + 2];
            v.w = acc[i][j + 3] + bias[col + 3];
            if (doRelu) {
                v.x = fmaxf(v.x, 0.0f); v.y = fmaxf(v.y, 0.0f);
                v.z = fmaxf(v.z, 0.0f); v.w = fmaxf(v.w, 0.0f);
            }
            *(float4*)&Y[row * BN + col] = v;
        }
    }
}

// ---------------- l2 normalize rows of [N, 64] in place ----------------------
__global__ void l2norm_kernel(float* __restrict__ z) {
    int r = blockIdx.x * blockDim.x + threadIdx.x;
    if (r >= NNODES) return;
    float4* p = (float4*)(z + r * 64);
    float4 v[16];
    float s = 0.0f;
#pragma unroll
    for (int i = 0; i < 16; i++) {
        v[i] = p[i];
        s += v[i].x * v[i].x + v[i].y * v[i].y + v[i].z * v[i].z + v[i].w * v[i].w;
    }
    float nrm = sqrtf(s);
    float inv = 1.0f / fmaxf(nrm, 1e-12f);
#pragma unroll
    for (int i = 0; i < 16; i++) {
        v[i].x *= inv; v[i].y *= inv; v[i].z *= inv; v[i].w *= inv;
        p[i] = v[i];
    }
}

// ---------------- final null head dot: out[r] = n1[r,:] . Wn2 + bn2 ----------
__global__ void null_kernel(const float* __restrict__ n1,
                            const float* __restrict__ Wn2,
                            const float* __restrict__ bn2,
                            float* __restrict__ out) {
    int r = blockIdx.x * blockDim.x + threadIdx.x;
    if (r >= NNODES) return;
    const float4* a = (const float4*)(n1 + r * 64);
    const float4* w = (const float4*)Wn2;
    float s = bn2[0];
#pragma unroll
    for (int i = 0; i < 16; i++) {
        float4 av = a[i];
        float4 wv = __ldg(&w[i]);
        s += av.x * wv.x + av.y * wv.y + av.z * wv.z + av.w * wv.w;
    }
    out[r] = s;
}

// ---------------- launch ------------------------------------------------------

extern "C" void kernel_launch(void* const* d_in, const int* in_sizes, int n_in,
                              void* d_out, int out_size) {
    const float* xA  = (const float*)d_in[0];
    const float* xB  = (const float*)d_in[1];
    const int*   eA  = (const int*)d_in[2];
    const int*   eB  = (const int*)d_in[3];
    const float* W1  = (const float*)d_in[4];
    const float* b1  = (const float*)d_in[5];
    const float* W2  = (const float*)d_in[6];
    const float* b2  = (const float*)d_in[7];
    const float* Wp1 = (const float*)d_in[8];
    const float* bp1 = (const float*)d_in[9];
    const float* Wp2 = (const float*)d_in[10];
    const float* bp2 = (const float*)d_in[11];
    const float* Wn1 = (const float*)d_in[12];
    const float* bn1 = (const float*)d_in[13];
    const float* Wn2 = (const float*)d_in[14];
    const float* bn2 = (const float*)d_in[15];

    float* out = (float*)d_out;
    float* hA = out;
    float* hB = out + (size_t)NNODES * 128;
    float* zA = out + (size_t)2 * NNODES * 128;
    float* zB = zA + (size_t)NNODES * 64;
    float* nullA = out + (size_t)2 * NNODES * 128 + (size_t)2 * NNODES * 64;
    float* nullB = nullA + NNODES;

    void* p;
    int* degcur;   cudaGetSymbolAddress(&p, g_degcur);  degcur  = (int*)p;
    int* rowptr;   cudaGetSymbolAddress(&p, g_rowptr);  rowptr  = (int*)p;
    int* csrc;     cudaGetSymbolAddress(&p, g_csr_src); csrc    = (int*)p;
    float* cw;     cudaGetSymbolAddress(&p, g_csr_w);   cw      = (float*)p;
    float* nrm;    cudaGetSymbolAddress(&p, g_norm);    nrm     = (float*)p;
    float* agg;    cudaGetSymbolAddress(&p, g_agg);     agg     = (float*)p;
    float* hid;    cudaGetSymbolAddress(&p, g_hid);     hid     = (float*)p;
    float* tmp;    cudaGetSymbolAddress(&p, g_tmp);     tmp     = (float*)p;

    cudaMemsetAsync(degcur, 0, 2 * NNODES * sizeof(int));
    degree_kernel<<<(2 * NEDGES + 255) / 256, 256>>>(eA, eB);
    norm_kernel<<<(2 * NNODES + 255) / 256, 256>>>();
    scan_kernel<<<2, 1024>>>();
    fill_kernel<<<(2 * NEDGES + 255) / 256, 256>>>(eA, eB);

    const int gemmGrid = (NNODES + 127) / 128;
    const int aggGrid  = (NNODES * 32 + 255) / 256;

    for (int g = 0; g < 2; g++) {
        const float* x  = g ? xB : xA;
        float* h        = g ? hB : hA;
        float* z        = g ? zB : zA;
        float* nl       = g ? nullB : nullA;
        const int* rp   = rowptr + g * (NNODES + 1);
        const int* cs   = csrc + (size_t)g * NEDGES;
        const float* wc = cw + (size_t)g * NEDGES;
        const float* nm = nrm + (size_t)g * NNODES;

        // layer 1: aggregate x, then h1 = relu(agg @ W1 + b1)
        agg_kernel<<<aggGrid, 256>>>(x, rp, cs, wc, nm, agg);
        gemm_kernel<128><<<gemmGrid, 256>>>(agg, 128, nullptr, 0, W1, b1, hid, NNODES, 1);
        // layer 2: aggregate h1, then h = agg @ W2 + b2   (encoder output)
        agg_kernel<<<aggGrid, 256>>>(hid, rp, cs, wc, nm, agg);
        gemm_kernel<128><<<gemmGrid, 256>>>(agg, 128, nullptr, 0, W2, b2, h, NNODES, 0);
        // proj MLP: z = relu(h@Wp1+bp1) @ Wp2 + bp2, then row-l2norm
        gemm_kernel<64><<<gemmGrid, 256>>>(h, 128, nullptr, 0, Wp1, bp1, tmp, NNODES, 1);
        gemm_kernel<64><<<gemmGrid, 256>>>(tmp, 64, nullptr, 0, Wp2, bp2, z, NNODES, 0);
        l2norm_kernel<<<(NNODES + 255) / 256, 256>>>(z);
        // null head: relu([h|z] @ Wn1 + bn1) @ Wn2 + bn2
        gemm_kernel<64><<<gemmGrid, 256>>>(h, 128, z, 64, Wn1, bn1, tmp, NNODES, 1);
        null_kernel<<<(NNODES + 255) / 256, 256>>>(tmp, Wn2, bn2, nl);
    }
}

// round 3
// speedup vs baseline: 1.9424x; 1.9424x over previous
#include <cuda_runtime.h>
#include <math.h>
#include <stdint.h>

#define NNODES 50000
#define NEDGES 800000
#define NTOT   (2 * NNODES)

// ---------------- scratch (device globals; no allocations allowed) ----------
__device__ int   g_degcur[NTOT];
__device__ int   g_rowptr[2 * (NNODES + 1)];
__device__ int   g_csr_src[2 * NEDGES];        // unified src ids (graph B +NNODES)
__device__ float g_csr_w[2 * NEDGES];
__device__ float g_norm[NTOT];
__device__ float g_agg[NTOT * 128];
__device__ float g_hid[NTOT * 128];
__device__ float g_tmp[NTOT * 64];

// ---------------- graph preprocessing ---------------------------------------

__global__ void degree_kernel(const int* __restrict__ eA, const int* __restrict__ eB) {
    int i = blockIdx.x * blockDim.x + threadIdx.x;
    if (i >= 2 * NEDGES) return;
    int g = i / NEDGES, e = i - g * NEDGES;
    const int* ei = g ? eB : eA;
    int dst = ei[NEDGES + e];
    atomicAdd(&g_degcur[g * NNODES + dst], 1);
}

__global__ void norm_kernel() {
    int i = blockIdx.x * blockDim.x + threadIdx.x;
    if (i >= NTOT) return;
    g_norm[i] = rsqrtf((float)g_degcur[i] + 1.0f);
}

// one block per graph: exclusive scan of degrees -> rowptr, init fill cursor
__global__ void scan_kernel() {
    __shared__ int sm[1024];
    int g = blockIdx.x;
    int t = threadIdx.x;
    const int CH = (NNODES + 1023) / 1024;
    int base = g * NNODES;
    int start = t * CH;
    int s = 0;
    for (int i = 0; i < CH; i++) {
        int idx = start + i;
        if (idx < NNODES) s += g_degcur[base + idx];
    }
    sm[t] = s;
    __syncthreads();
    for (int d = 1; d < 1024; d <<= 1) {
        int v = sm[t];
        int add = (t >= d) ? sm[t - d] : 0;
        __syncthreads();
        sm[t] = v + add;
        __syncthreads();
    }
    int off = (t == 0) ? 0 : sm[t - 1];
    for (int i = 0; i < CH; i++) {
        int idx = start + i;
        if (idx < NNODES) {
            int d = g_degcur[base + idx];
            g_rowptr[g * (NNODES + 1) + idx] = off;
            g_degcur[base + idx] = off;
            off += d;
        }
    }
    if (t == 1023) g_rowptr[g * (NNODES + 1) + NNODES] = off;
}

__global__ void fill_kernel(const int* __restrict__ eA, const int* __restrict__ eB) {
    int i = blockIdx.x * blockDim.x + threadIdx.x;
    if (i >= 2 * NEDGES) return;
    int g = i / NEDGES, e = i - g * NEDGES;
    const int* ei = g ? eB : eA;
    int src = ei[e];
    int dst = ei[NEDGES + e];
    int pos = atomicAdd(&g_degcur[g * NNODES + dst], 1);
    int su = src + g * NNODES;
    int du = dst + g * NNODES;
    g_csr_src[g * NEDGES + pos] = su;
    g_csr_w[g * NEDGES + pos]   = g_norm[su] * g_norm[du];
}

// ---------------- GCN aggregation: warp per node (unified 2N) ----------------
__global__ void agg_kernel(const float* __restrict__ x1,
                           const float* __restrict__ x2,
                           float* __restrict__ out) {
    int node = (blockIdx.x * blockDim.x + threadIdx.x) >> 5;
    int lane = threadIdx.x & 31;
    if (node >= NTOT) return;
    int g = (node >= NNODES);
    int local = node - (g ? NNODES : 0);
    const float4* xs = (const float4*)(g ? x2 : x1);
    const float4* x1v = (const float4*)x1;
    const float4* x2v = (const float4*)x2;

    float nn = g_norm[node];
    float c = nn * nn;
    float4 a = __ldg(&xs[local * 32 + lane]);
    float4 acc;
    acc.x = a.x * c; acc.y = a.y * c; acc.z = a.z * c; acc.w = a.w * c;

    int b  = g_rowptr[g * (NNODES + 1) + local]     + g * NEDGES;
    int en = g_rowptr[g * (NNODES + 1) + local + 1] + g * NEDGES;
    for (int e = b; e < en; e++) {
        int s   = __ldg(&g_csr_src[e]);
        float w = __ldg(&g_csr_w[e]);
        int sg = (s >= NNODES);
        const float4* xr = sg ? x2v : x1v;
        int sl = s - (sg ? NNODES : 0);
        float4 v = __ldg(&xr[sl * 32 + lane]);
        acc.x += v.x * w; acc.y += v.y * w; acc.z += v.z * w; acc.w += v.w * w;
    }
    ((float4*)out)[node * 32 + lane] = acc;
}

// ---------------- TF32 tensor-core GEMM --------------------------------------
// Y[n x BN] = epi( X[n x K] @ W[K x BN] + bias ),  X = concat(X1[K1], X2[K2])
// BM=128, BK=32, 256 threads. EPI: 0 none, 1 relu, 2 l2norm-row, 3 relu+dot(Wn2)+bn2
#define ASTRIDE 36

__device__ __forceinline__ uint32_t f2tf32(float f) {
    uint32_t u;
    asm volatile("cvt.rna.tf32.f32 %0, %1;" : "=r"(u) : "f"(f));
    return u;
}
__device__ __forceinline__ void cpasync16(uint32_t dst, const void* src, bool pred) {
    int sz = pred ? 16 : 0;
    asm volatile("cp.async.cg.shared.global [%0], [%1], 16, %2;"
                 :: "r"(dst), "l"(src), "r"(sz));
}
__device__ __forceinline__ void mma_tf32(float* c, const uint32_t* a, const uint32_t* b) {
    asm volatile(
        "mma.sync.aligned.m16n8k8.row.col.f32.tf32.tf32.f32 "
        "{%0,%1,%2,%3}, {%4,%5,%6,%7}, {%8,%9}, {%0,%1,%2,%3};"
        : "+f"(c[0]), "+f"(c[1]), "+f"(c[2]), "+f"(c[3])
        : "r"(a[0]), "r"(a[1]), "r"(a[2]), "r"(a[3]), "r"(b[0]), "r"(b[1]));
}

template <int BN, int MT, int EPI>
__global__ void gemm_tc(const float* __restrict__ X1, int K1,
                        const float* __restrict__ X2, int K2,
                        const float* __restrict__ W,
                        const float* __restrict__ bias,
                        float* __restrict__ Y, int n,
                        const float* __restrict__ Wn2,
                        const float* __restrict__ bn2) {
    constexpr int SB = BN + 8;
    extern __shared__ float sm[];
    float* Ab = sm;                       // 2 * 128 * ASTRIDE
    float* Bb = sm + 2 * 128 * ASTRIDE;   // 2 * 32 * SB

    const int t = threadIdx.x;
    const int wid = t >> 5;
    const int lane = t & 31;
    const int lr = lane >> 2;     // 0..7
    const int lc = lane & 3;      // 0..3
    const int K = K1 + K2;
    const int T = K / 32;
    const int row0 = blockIdx.x * 128;

    constexpr int WROWS = (BN == 128) ? 4 : 8;
    const int warpRow = (wid % WROWS) * (MT * 16);
    const int warpCol = (wid / WROWS) * 64;

    float acc[MT][8][4];
#pragma unroll
    for (int m = 0; m < MT; m++)
#pragma unroll
        for (int nt = 0; nt < 8; nt++)
#pragma unroll
            for (int j = 0; j < 4; j++) acc[m][nt][j] = 0.0f;

    uint32_t aBase = (uint32_t)__cvta_generic_to_shared(Ab);
    uint32_t bBase = (uint32_t)__cvta_generic_to_shared(Bb);

    auto loadA = [&](int buf, int k0) {
#pragma unroll
        for (int i = 0; i < 4; i++) {
            int idx4 = t + i * 256;           // 0..1023
            int row = idx4 >> 3;              // 0..127
            int kq = idx4 & 7;
            int kg = k0 + 4 * kq;
            int rg = row0 + row;
            const float* src = (kg < K1) ? (X1 + (size_t)rg * K1 + kg)
                                         : (X2 + (size_t)rg * K2 + (kg - K1));
            uint32_t dst = aBase + (uint32_t)((buf * 128 * ASTRIDE + row * ASTRIDE + 4 * kq) * 4);
            cpasync16(dst, src, rg < n);
        }
    };
    auto loadB = [&](int buf, int k0) {
        constexpr int ITER = (32 * BN) / (256 * 4);
#pragma unroll
        for (int i = 0; i < ITER; i++) {
            int idx4 = t + i * 256;
            int k = idx4 / (BN / 4);
            int cq = idx4 % (BN / 4);
            const float* src = W + (size_t)(k0 + k) * BN + 4 * cq;
            uint32_t dst = bBase + (uint32_t)((buf * 32 * SB + k * SB + 4 * cq) * 4);
            cpasync16(dst, src, true);
        }
    };

    loadA(0, 0);
    loadB(0, 0);
    asm volatile("cp.async.commit_group;");

    for (int tt = 0; tt < T; tt++) {
        int buf = tt & 1;
        if (tt + 1 < T) {
            loadA(buf ^ 1, (tt + 1) * 32);
            loadB(buf ^ 1, (tt + 1) * 32);
            asm volatile("cp.async.commit_group;");
            asm volatile("cp.async.wait_group 1;");
        } else {
            asm volatile("cp.async.wait_group 0;");
        }
        __syncthreads();

        const float* As = Ab + buf * 128 * ASTRIDE;
        const float* Bs = Bb + buf * 32 * SB;
#pragma unroll
        for (int kk8 = 0; kk8 < 4; kk8++) {
            int kb = kk8 * 8;
            uint32_t af[MT][4];
#pragma unroll
            for (int m = 0; m < MT; m++) {
                int r1 = warpRow + m * 16 + lr;
                af[m][0] = f2tf32(As[r1 * ASTRIDE + kb + lc]);
                af[m][1] = f2tf32(As[(r1 + 8) * ASTRIDE + kb + lc]);
                af[m][2] = f2tf32(As[r1 * ASTRIDE + kb + lc + 4]);
                af[m][3] = f2tf32(As[(r1 + 8) * ASTRIDE + kb + lc + 4]);
            }
            uint32_t bf[8][2];
#pragma unroll
            for (int nt = 0; nt < 8; nt++) {
                int cc = warpCol + nt * 8 + lr;
                bf[nt][0] = f2tf32(Bs[(kb + lc) * SB + cc]);
                bf[nt][1] = f2tf32(Bs[(kb + lc + 4) * SB + cc]);
            }
#pragma unroll
            for (int m = 0; m < MT; m++)
#pragma unroll
                for (int nt = 0; nt < 8; nt++)
                    mma_tf32(acc[m][nt], af[m], bf[nt]);
        }
        __syncthreads();
    }

    // ----------------- epilogue -----------------
#pragma unroll
    for (int m = 0; m < MT; m++) {
        int r1 = row0 + warpRow + m * 16 + lr;
        int r2 = r1 + 8;

        // bias (+relu for EPI 1/3)
        float v[8][4];
#pragma unroll
        for (int nt = 0; nt < 8; nt++) {
            int col = warpCol + nt * 8 + 2 * lc;
            float b0 = __ldg(&bias[col]);
            float b1 = __ldg(&bias[col + 1]);
            v[nt][0] = acc[m][nt][0] + b0;
            v[nt][1] = acc[m][nt][1] + b1;
            v[nt][2] = acc[m][nt][2] + b0;
            v[nt][3] = acc[m][nt][3] + b1;
            if (EPI == 1 || EPI == 3) {
#pragma unroll
                for (int j = 0; j < 4; j++) v[nt][j] = fmaxf(v[nt][j], 0.0f);
            }
        }

        if (EPI == 0 || EPI == 1) {
#pragma unroll
            for (int nt = 0; nt < 8; nt++) {
                int col = warpCol + nt * 8 + 2 * lc;
                if (r1 < n) { float2 s = {v[nt][0], v[nt][1]}; *(float2*)&Y[(size_t)r1 * BN + col] = s; }
                if (r2 < n) { float2 s = {v[nt][2], v[nt][3]}; *(float2*)&Y[(size_t)r2 * BN + col] = s; }
            }
        } else if (EPI == 2) {
            // row l2 norm (BN==64: warp owns full rows)
            float s1 = 0.0f, s2 = 0.0f;
#pragma unroll
            for (int nt = 0; nt < 8; nt++) {
                s1 += v[nt][0] * v[nt][0] + v[nt][1] * v[nt][1];
                s2 += v[nt][2] * v[nt][2] + v[nt][3] * v[nt][3];
            }
            s1 += __shfl_xor_sync(0xffffffffu, s1, 1);
            s1 += __shfl_xor_sync(0xffffffffu, s1, 2);
            s2 += __shfl_xor_sync(0xffffffffu, s2, 1);
            s2 += __shfl_xor_sync(0xffffffffu, s2, 2);
            float i1 = 1.0f / fmaxf(sqrtf(s1), 1e-12f);
            float i2 = 1.0f / fmaxf(sqrtf(s2), 1e-12f);
#pragma unroll
            for (int nt = 0; nt < 8; nt++) {
                int col = warpCol + nt * 8 + 2 * lc;
                if (r1 < n) { float2 s = {v[nt][0] * i1, v[nt][1] * i1}; *(float2*)&Y[(size_t)r1 * BN + col] = s; }
                if (r2 < n) { float2 s = {v[nt][2] * i2, v[nt][3] * i2}; *(float2*)&Y[(size_t)r2 * BN + col] = s; }
            }
        } else { // EPI == 3: dot with Wn2, +bn2, write scalar per row
            float d1 = 0.0f, d2 = 0.0f;
#pragma unroll
            for (int nt = 0; nt < 8; nt++) {
                int col = warpCol + nt * 8 + 2 * lc;
                float w0 = __ldg(&Wn2[col]);
                float w1 = __ldg(&Wn2[col + 1]);
                d1 += v[nt][0] * w0 + v[nt][1] * w1;
                d2 += v[nt][2] * w0 + v[nt][3] * w1;
            }
            d1 += __shfl_xor_sync(0xffffffffu, d1, 1);
            d1 += __shfl_xor_sync(0xffffffffu, d1, 2);
            d2 += __shfl_xor_sync(0xffffffffu, d2, 1);
            d2 += __shfl_xor_sync(0xffffffffu, d2, 2);
            if (lc == 0) {
                float bb = __ldg(&bn2[0]);
                if (r1 < n) Y[r1] = d1 + bb;
                if (r2 < n) Y[r2] = d2 + bb;
            }
        }
    }
}

// ---------------- launch ------------------------------------------------------

extern "C" void kernel_launch(void* const* d_in, const int* in_sizes, int n_in,
                              void* d_out, int out_size) {
    const float* xA  = (const float*)d_in[0];
    const float* xB  = (const float*)d_in[1];
    const int*   eA  = (const int*)d_in[2];
    const int*   eB  = (const int*)d_in[3];
    const float* W1  = (const float*)d_in[4];
    const float* b1  = (const float*)d_in[5];
    const float* W2  = (const float*)d_in[6];
    const float* b2  = (const float*)d_in[7];
    const float* Wp1 = (const float*)d_in[8];
    const float* bp1 = (const float*)d_in[9];
    const float* Wp2 = (const float*)d_in[10];
    const float* bp2 = (const float*)d_in[11];
    const float* Wn1 = (const float*)d_in[12];
    const float* bn1 = (const float*)d_in[13];
    const float* Wn2 = (const float*)d_in[14];
    const float* bn2 = (const float*)d_in[15];

    float* out  = (float*)d_out;
    float* h    = out;                               // [2N,128] (hA | hB)
    float* z    = out + (size_t)NTOT * 128;          // [2N,64]
    float* nul  = z + (size_t)NTOT * 64;             // [2N]

    void* p;
    int* degcur;  cudaGetSymbolAddress(&p, g_degcur); degcur = (int*)p;
    float* agg;   cudaGetSymbolAddress(&p, g_agg);    agg    = (float*)p;
    float* hid;   cudaGetSymbolAddress(&p, g_hid);    hid    = (float*)p;
    float* tmp;   cudaGetSymbolAddress(&p, g_tmp);    tmp    = (float*)p;

    cudaMemsetAsync(degcur, 0, NTOT * sizeof(int));
    degree_kernel<<<(2 * NEDGES + 255) / 256, 256>>>(eA, eB);
    norm_kernel<<<(NTOT + 255) / 256, 256>>>();
    scan_kernel<<<2, 1024>>>();
    fill_kernel<<<(2 * NEDGES + 255) / 256, 256>>>(eA, eB);

    const int gemmGrid = (NTOT + 127) / 128;
    const int aggGrid  = (NTOT * 32 + 255) / 256;

    size_t sh128 = (2 * 128 * ASTRIDE + 2 * 32 * (128 + 8)) * sizeof(float);
    size_t sh64  = (2 * 128 * ASTRIDE + 2 * 32 * (64 + 8)) * sizeof(float);
    cudaFuncSetAttribute(gemm_tc<128, 2, 1>, cudaFuncAttributeMaxDynamicSharedMemorySize, (int)sh128);
    cudaFuncSetAttribute(gemm_tc<128, 2, 0>, cudaFuncAttributeMaxDynamicSharedMemorySize, (int)sh128);
    cudaFuncSetAttribute(gemm_tc<64, 1, 1>,  cudaFuncAttributeMaxDynamicSharedMemorySize, (int)sh64);
    cudaFuncSetAttribute(gemm_tc<64, 1, 2>,  cudaFuncAttributeMaxDynamicSharedMemorySize, (int)sh64);
    cudaFuncSetAttribute(gemm_tc<64, 1, 3>,  cudaFuncAttributeMaxDynamicSharedMemorySize, (int)sh64);

    // layer 1: agg(x) -> relu(. @ W1 + b1)
    agg_kernel<<<aggGrid, 256>>>(xA, xB, agg);
    gemm_tc<128, 2, 1><<<gemmGrid, 256, sh128>>>(agg, 128, nullptr, 0, W1, b1, hid, NTOT, nullptr, nullptr);
    // layer 2: agg(h1) -> . @ W2 + b2   (encoder output h)
    agg_kernel<<<aggGrid, 256>>>(hid, hid + (size_t)NNODES * 128, agg);
    gemm_tc<128, 2, 0><<<gemmGrid, 256, sh128>>>(agg, 128, nullptr, 0, W2, b2, h, NTOT, nullptr, nullptr);
    // proj: relu(h@Wp1+bp1) -> @Wp2+bp2 -> row-l2norm (fused)
    gemm_tc<64, 1, 1><<<gemmGrid, 256, sh64>>>(h, 128, nullptr, 0, Wp1, bp1, tmp, NTOT, nullptr, nullptr);
    gemm_tc<64, 1, 2><<<gemmGrid, 256, sh64>>>(tmp, 64, nullptr, 0, Wp2, bp2, z, NTOT, nullptr, nullptr);
    // null head: relu([h|z]@Wn1+bn1) . Wn2 + bn2 (fused dot)
    gemm_tc<64, 1, 3><<<gemmGrid, 256, sh64>>>(h, 128, z, 64, Wn1, bn1, nul, NTOT, Wn2, bn2);
}